// round 11
// baseline (speedup 1.0000x reference)
#include <cuda_runtime.h>
#include <cuda_fp16.h>
#include <cstdint>
#include <math.h>

#define DD 128
#define NPTHREADS 256
#define ETH 256

// Device scratch
__device__ float  g_agg[(size_t)50000 * 128];
__device__ float  g_P[(size_t)50000 * 256];
__device__ __half g_w1h[256 * 256];   // [n][k] n-major: W1 (state|eattr rows), msg|att
__device__ __half g_w2h[256 * 128];   // [n][k] n-major: W2 msg|att
__device__ __half g_wefh[256 * 32];   // [n][k] n-major: W1 EF rows, msg|att

__device__ __forceinline__ float sigmoidf_fast(float x) {
    return 1.0f / (1.0f + __expf(-x));
}
__device__ __forceinline__ void mma_f16(float c[4], const unsigned a[4], const unsigned b[2]) {
    asm volatile(
        "mma.sync.aligned.m16n8k16.row.col.f32.f16.f16.f32 "
        "{%0,%1,%2,%3}, {%4,%5,%6,%7}, {%8,%9}, {%0,%1,%2,%3};"
        : "+f"(c[0]), "+f"(c[1]), "+f"(c[2]), "+f"(c[3])
        : "r"(a[0]), "r"(a[1]), "r"(a[2]), "r"(a[3]), "r"(b[0]), "r"(b[1]));
}
__device__ __forceinline__ uint32_t pack_h2(float lo, float hi) {
    __half2 h = __floats2half2_rn(lo, hi);
    return *(uint32_t*)&h;
}

__global__ void zero_agg_kernel() {
    size_t i = (size_t)blockIdx.x * blockDim.x + threadIdx.x;
    if (i < (size_t)50000 * 128) g_agg[i] = 0.0f;
}

// One-time transpose/convert of weights into n-major fp16 device tables.
__global__ void prep_kernel(const float* __restrict__ msg_w1,
                            const float* __restrict__ att_w1,
                            const float* __restrict__ msg_w2,
                            const float* __restrict__ att_w2)
{
    int i = blockIdx.x * 256 + threadIdx.x;   // 0 .. 65535
    if (i < 32768) {            // g_w2h [256][128]
        int n = i >> 7, k = i & 127;
        float v = (n < 128) ? msg_w2[k * 128 + n] : att_w2[k * 128 + (n - 128)];
        g_w2h[i] = __float2half_rn(v);
    }
    if (i < 8192) {             // g_wefh [256][32]
        int n = i >> 5, k = i & 31;
        float v = (n < 128) ? msg_w1[(128 + k) * 128 + n] : att_w1[(128 + k) * 128 + (n - 128)];
        g_wefh[i] = __float2half_rn(v);
    }
    if (i < 65536) {            // g_w1h [256][256]
        int n = i >> 8, k = i & 255;
        int wrow = (k < 128) ? k : (k + 32);     // skip EF rows 128..159
        float v = (n < 128) ? msg_w1[wrow * 128 + n] : att_w1[wrow * 128 + (n - 128)];
        g_w1h[i] = __float2half_rn(v);
    }
}

// ===================== Node projection kernel (fp16 HMMA) =====================
// P[n][c] = state[n]@W1[0:128] + eattr[n]@W1[160:288] + na terms (f32)
#define NPXS 20   // xs word stride (16 words data + 4 pad)
extern "C" __global__ void __launch_bounds__(NPTHREADS)
nodeproj_kernel(const float* __restrict__ node_feat,
                const float* __restrict__ node_attr,   // [2][N]
                const float* __restrict__ edge_attr,   // [N][128]
                const float* __restrict__ msg_w1,
                const float* __restrict__ att_w1,
                int N_)
{
    __shared__ uint32_t xs[64 * NPXS];
    __shared__ float wna[2][256];

    const int tid  = threadIdx.x;
    const int lane = tid & 31;
    const int wid  = tid >> 5;
    const int g    = lane >> 2;
    const int tg   = lane & 3;
    const int mg   = wid & 1;        // rows 32*mg
    const int ng   = wid >> 1;       // cols 64*ng
    const int n0   = blockIdx.x * 64;

    for (int c = tid; c < 256; c += NPTHREADS) {
        const float* w1 = (c < 128) ? msg_w1 : att_w1;
        int cc = c & 127;
        wna[0][c] = w1[288 * 128 + cc];
        wna[1][c] = w1[289 * 128 + cc];
    }

    float acc[2][8][4];
    #pragma unroll
    for (int mt = 0; mt < 2; ++mt)
        #pragma unroll
        for (int nt = 0; nt < 8; ++nt)
            #pragma unroll
            for (int c = 0; c < 4; ++c) acc[mt][nt][c] = 0.f;

    for (int s = 0; s < 8; ++s) {
        const int k0 = 32 * s;
        // A slab [64 rows][32 halves] packed fp16
        for (int idx = tid; idx < 64 * 16; idx += NPTHREADS) {
            int row = idx >> 4, w = idx & 15;
            int n = n0 + row;
            float v0 = 0.f, v1 = 0.f;
            if (n < N_) {
                int k = k0 + 2 * w;
                if (k < 128) {
                    v0 = node_feat[(size_t)n * 128 + k];
                    v1 = node_feat[(size_t)n * 128 + k + 1];
                } else {
                    v0 = edge_attr[(size_t)n * 128 + (k - 128)];
                    v1 = edge_attr[(size_t)n * 128 + (k - 128) + 1];
                }
            }
            xs[row * NPXS + w] = pack_h2(v0, v1);
        }
        __syncthreads();
        const int k0w = s * 16;   // global word offset into g_w1h rows
        #pragma unroll
        for (int ks = 0; ks < 2; ++ks) {
            const int klw = ks * 8;
            unsigned a[2][4];
            #pragma unroll
            for (int mt = 0; mt < 2; ++mt) {
                int row = 32 * mg + 16 * mt + g;
                a[mt][0] = xs[row * NPXS + klw + tg];
                a[mt][1] = xs[(row + 8) * NPXS + klw + tg];
                a[mt][2] = xs[row * NPXS + klw + tg + 4];
                a[mt][3] = xs[(row + 8) * NPXS + klw + tg + 4];
            }
            #pragma unroll
            for (int nt = 0; nt < 8; ++nt) {
                int n = 64 * ng + 8 * nt + g;
                const uint32_t* wrow = (const uint32_t*)(g_w1h + (size_t)n * 256);
                unsigned b[2];
                b[0] = __ldg(wrow + k0w + klw + tg);
                b[1] = __ldg(wrow + k0w + klw + tg + 4);
                mma_f16(acc[0][nt], a[0], b);
                mma_f16(acc[1][nt], a[1], b);
            }
        }
        __syncthreads();
    }

    #pragma unroll
    for (int mt = 0; mt < 2; ++mt)
        #pragma unroll
        for (int c = 0; c < 4; ++c) {
            int r = 32 * mg + 16 * mt + g + 8 * (c >> 1);
            int n = n0 + r;
            if (n >= N_) continue;
            float na0 = node_attr[n];
            float na1 = node_attr[N_ + n];
            #pragma unroll
            for (int nt = 0; nt < 8; ++nt) {
                int col = 64 * ng + 8 * nt + 2 * tg + (c & 1);
                g_P[(size_t)n * 256 + col] =
                    acc[mt][nt][c] + na0 * wna[0][col] + na1 * wna[1][col];
            }
        }
}

// ===================== Edge kernel (TILE 32, 256 thr, 2 CTAs/SM) =====================
// Dynamic smem (bytes):
//   xs   [32 r][20 w]  fp16-packed   2560
//   h    [32 r][132 w] fp16-packed  16896   (relu layer-1 out, msg|att)
//   pre  [32 r][260 f32]            33280   (P-diff / final exchange)
//   sd   64 int                       256
#define XS_OFF   0
#define H_OFF    2560
#define PRE_OFF  19456
#define SD_OFF   52736
#define EDGE_SMEM_BYTES 53248
#define LDXSW 20
#define LDHW  132
#define LDP   260

extern "C" __global__ void __launch_bounds__(ETH, 2)
edge_kernel(const int*   __restrict__ edge,
            const float* __restrict__ edge_feat,
            const float* __restrict__ msg_b1, const float* __restrict__ msg_b2,
            const float* __restrict__ att_b1, const float* __restrict__ att_b2,
            int M_, int t0, int t1)
{
    extern __shared__ char smraw[];
    uint32_t* xs32 = (uint32_t*)(smraw + XS_OFF);
    uint32_t* h32  = (uint32_t*)(smraw + H_OFF);
    float*    pref = (float*)(smraw + PRE_OFF);
    int*      sd   = (int*)(smraw + SD_OFF);

    const int tid  = threadIdx.x;
    const int lane = tid & 31;
    const int wid  = tid >> 5;          // 0..7
    const int g    = lane >> 2;
    const int tg   = lane & 3;
    const int mg   = wid & 1;           // rows 16*mg
    const int ng   = wid >> 1;          // cols 64*ng
    const int br   = ng >> 1;           // 0=msg, 1=att
    const int koffw = br * 64;          // branch k offset into h (words)
    const int r0   = 16 * mg;
    const int c0   = 64 * ng;

    // EF B-fragments are tile-invariant: preload to registers.
    unsigned bef[2][8][2];
    #pragma unroll
    for (int ks = 0; ks < 2; ++ks)
        #pragma unroll
        for (int nt = 0; nt < 8; ++nt) {
            int n = c0 + 8 * nt + g;
            const uint32_t* wrow = (const uint32_t*)(g_wefh + (size_t)n * 32);
            bef[ks][nt][0] = __ldg(wrow + ks * 8 + tg);
            bef[ks][nt][1] = __ldg(wrow + ks * 8 + tg + 4);
        }

    for (int t = t0 + blockIdx.x; t < t1; t += gridDim.x) {
        const int e0 = t << 5;

        // ---- Phase A: endpoints + EF -> xs ----
        if (tid < 32) {
            int ge = e0 + tid;
            int s = 0, d = 0;
            if (ge < M_) { s = edge[2 * ge]; d = edge[2 * ge + 1]; }
            sd[tid] = s;
            sd[32 + tid] = d;
        }
        for (int idx = tid; idx < 32 * 16; idx += ETH) {
            int row = idx >> 4, w = idx & 15;
            int ge = e0 + row;
            float v0 = 0.f, v1 = 0.f;
            if (ge < M_) {
                v0 = edge_feat[(size_t)ge * 32 + 2 * w];
                v1 = edge_feat[(size_t)ge * 32 + 2 * w + 1];
            }
            xs32[row * LDXSW + w] = pack_h2(v0, v1);
        }
        __syncthreads();

        // ---- Phase B: P-diff gather (LDG issue first) + EF mma ----
        for (int idx = tid; idx < 32 * 64; idx += ETH) {
            int row = idx >> 6, c4 = idx & 63;
            const float4* ps = (const float4*)(g_P + (size_t)sd[row] * 256) + c4;
            const float4* pd = (const float4*)(g_P + (size_t)sd[32 + row] * 256) + c4;
            float4 a = *ps, b = *pd;
            float4 r;
            r.x = a.x - b.x; r.y = a.y - b.y; r.z = a.z - b.z; r.w = a.w - b.w;
            *(float4*)(pref + row * LDP + c4 * 4) = r;
        }

        float acc[8][4];
        #pragma unroll
        for (int nt = 0; nt < 8; ++nt)
            #pragma unroll
            for (int c = 0; c < 4; ++c) acc[nt][c] = 0.f;

        #pragma unroll
        for (int ks = 0; ks < 2; ++ks) {
            const int k0w = ks * 8;
            unsigned a[4];
            a[0] = xs32[(r0 + g) * LDXSW + k0w + tg];
            a[1] = xs32[(r0 + g + 8) * LDXSW + k0w + tg];
            a[2] = xs32[(r0 + g) * LDXSW + k0w + tg + 4];
            a[3] = xs32[(r0 + g + 8) * LDXSW + k0w + tg + 4];
            #pragma unroll
            for (int nt = 0; nt < 8; ++nt)
                mma_f16(acc[nt], a, bef[ks][nt]);
        }
        __syncthreads();

        // ---- Phase C: combine -> relu -> h (fp16) ----
        #pragma unroll
        for (int c2 = 0; c2 < 2; ++c2) {
            int r = r0 + g + 8 * c2;
            #pragma unroll
            for (int nt = 0; nt < 8; ++nt) {
                int colb = c0 + 8 * nt + 2 * tg;
                float b1a = (colb < 128) ? __ldg(msg_b1 + colb) : __ldg(att_b1 + colb - 128);
                float b1b = (colb < 128) ? __ldg(msg_b1 + colb + 1) : __ldg(att_b1 + colb - 127);
                float v0 = pref[r * LDP + colb]     + acc[nt][2 * c2]     + b1a;
                float v1 = pref[r * LDP + colb + 1] + acc[nt][2 * c2 + 1] + b1b;
                h32[r * LDHW + (colb >> 1)] = pack_h2(fmaxf(v0, 0.f), fmaxf(v1, 0.f));
            }
        }
        __syncthreads();

        // ---- Phase D: layer-2 mma (B-frags via L1-hot LDG) + exchange write ----
        #pragma unroll
        for (int nt = 0; nt < 8; ++nt)
            #pragma unroll
            for (int c = 0; c < 4; ++c) acc[nt][c] = 0.f;

        #pragma unroll
        for (int ks = 0; ks < 8; ++ks) {
            const int k0w = ks * 8;
            unsigned a[4];
            a[0] = h32[(r0 + g) * LDHW + koffw + k0w + tg];
            a[1] = h32[(r0 + g + 8) * LDHW + koffw + k0w + tg];
            a[2] = h32[(r0 + g) * LDHW + koffw + k0w + tg + 4];
            a[3] = h32[(r0 + g + 8) * LDHW + koffw + k0w + tg + 4];
            #pragma unroll
            for (int nt = 0; nt < 8; ++nt) {
                int n = c0 + 8 * nt + g;
                const uint32_t* wrow = (const uint32_t*)(g_w2h + (size_t)n * 128);
                unsigned b[2];
                b[0] = __ldg(wrow + k0w + tg);
                b[1] = __ldg(wrow + k0w + tg + 4);
                mma_f16(acc[nt], a, b);
            }
        }

        #pragma unroll
        for (int c = 0; c < 4; ++c) {
            int r = r0 + g + 8 * (c >> 1);
            #pragma unroll
            for (int nt = 0; nt < 8; ++nt) {
                int col = c0 + 8 * nt + 2 * tg + (c & 1);
                float b2 = (col < 128) ? __ldg(msg_b2 + col) : __ldg(att_b2 + col - 128);
                float v = acc[nt][c] + b2;
                if (br) v = sigmoidf_fast(v);
                pref[r * LDP + col] = v;
            }
        }
        __syncthreads();

        // ---- Phase E: gate + scatter ----
        for (int idx = tid; idx < 32 * 128; idx += ETH) {
            int row = idx >> 7, c = idx & 127;
            int ge = e0 + row;
            if (ge < M_) {
                float v = pref[row * LDP + c] * pref[row * LDP + 128 + c];
                atomicAdd(g_agg + (size_t)sd[32 + row] * 128 + c, v);
            }
        }
        __syncthreads();
    }
}

// ===================== GRU kernel =====================
extern "C" __global__ void __launch_bounds__(128)
gru_kernel(const float* __restrict__ node_feat,
           const float* __restrict__ w_ih,  // [384][128]
           const float* __restrict__ w_hh,  // [384][128]
           const float* __restrict__ b_ih,
           const float* __restrict__ b_hh,
           float* __restrict__ out, int N_)
{
    __shared__ __align__(16) float agg_s[8 * 128];
    __shared__ __align__(16) float st_s[8 * 128];
    __shared__ float gi_s[8 * 384];
    __shared__ float gh_s[8 * 384];

    const int tid = threadIdx.x;
    const int n0 = blockIdx.x * 8;

    for (int idx = tid; idx < 8 * 128; idx += 128) {
        int n = idx >> 7, c = idx & 127;
        int gn = n0 + n;
        float av = 0.f, sv = 0.f;
        if (gn < N_) {
            av = g_agg[(size_t)gn * 128 + c];
            sv = node_feat[(size_t)gn * 128 + c];
        }
        agg_s[idx] = av;
        st_s[idx]  = sv;
    }
    __syncthreads();

    for (int idx = tid; idx < 8 * 384; idx += 128) {
        int n = idx / 384;
        int j = idx - n * 384;
        const float4* wi4 = (const float4*)(w_ih + j * 128);
        const float4* wh4 = (const float4*)(w_hh + j * 128);
        const float4* x4  = (const float4*)(agg_s + n * 128);
        const float4* s4  = (const float4*)(st_s + n * 128);
        float si = 0.f, sh = 0.f;
        #pragma unroll 8
        for (int k = 0; k < 32; ++k) {
            float4 a = x4[k], b = wi4[k];
            si += a.x * b.x + a.y * b.y + a.z * b.z + a.w * b.w;
            float4 c = s4[k], d = wh4[k];
            sh += c.x * d.x + c.y * d.y + c.z * d.z + c.w * d.w;
        }
        gi_s[idx] = si + b_ih[j];
        gh_s[idx] = sh + b_hh[j];
    }
    __syncthreads();

    for (int idx = tid; idx < 8 * 128; idx += 128) {
        int n = idx >> 7, c = idx & 127;
        int gn = n0 + n;
        if (gn >= N_) continue;
        float ir = gi_s[n * 384 + c];
        float iz = gi_s[n * 384 + 128 + c];
        float in_ = gi_s[n * 384 + 256 + c];
        float hr = gh_s[n * 384 + c];
        float hz = gh_s[n * 384 + 128 + c];
        float hn = gh_s[n * 384 + 256 + c];
        float r = sigmoidf_fast(ir + hr);
        float z = sigmoidf_fast(iz + hz);
        float nv = tanhf(in_ + r * hn);
        out[(size_t)gn * 128 + c] = (1.0f - z) * nv + z * st_s[idx];
    }
}

extern "C" void kernel_launch(void* const* d_in, const int* in_sizes, int n_in,
                              void* d_out, int out_size)
{
    const float* node_feat = (const float*)d_in[0];
    const int*   edge      = (const int*)  d_in[1];
    const float* edge_feat = (const float*)d_in[2];
    const float* node_attr = (const float*)d_in[3];
    const float* edge_attr = (const float*)d_in[4];
    const float* msg_w1    = (const float*)d_in[5];
    const float* msg_b1    = (const float*)d_in[6];
    const float* msg_w2    = (const float*)d_in[7];
    const float* msg_b2    = (const float*)d_in[8];
    const float* att_w1    = (const float*)d_in[9];
    const float* att_b1    = (const float*)d_in[10];
    const float* att_w2    = (const float*)d_in[11];
    const float* att_b2    = (const float*)d_in[12];
    const float* gru_w_ih  = (const float*)d_in[13];
    const float* gru_w_hh  = (const float*)d_in[14];
    const float* gru_b_ih  = (const float*)d_in[15];
    const float* gru_b_hh  = (const float*)d_in[16];
    float* out = (float*)d_out;

    int N_ = in_sizes[0] / DD;
    int M_ = in_sizes[1] / 2;

    cudaFuncSetAttribute(edge_kernel, cudaFuncAttributeMaxDynamicSharedMemorySize,
                         EDGE_SMEM_BYTES);

    size_t tot = (size_t)N_ * DD;
    zero_agg_kernel<<<(int)((tot + 255) / 256), 256>>>();

    prep_kernel<<<256, 256>>>(msg_w1, att_w1, msg_w2, att_w2);

    int nblocks = (N_ + 63) / 64;
    nodeproj_kernel<<<nblocks, NPTHREADS>>>(node_feat, node_attr, edge_attr,
                                            msg_w1, att_w1, N_);

    int ntiles = (M_ + 31) / 32;
    // 4 sequential quarter launches (profiling visibility)
    for (int q = 0; q < 4; ++q) {
        int t0 = (ntiles * q) / 4;
        int t1 = (ntiles * (q + 1)) / 4;
        int nt = t1 - t0;
        if (nt <= 0) continue;
        int egrid = nt < 296 ? nt : 296;
        edge_kernel<<<egrid, ETH, EDGE_SMEM_BYTES>>>(
            edge, edge_feat, msg_b1, msg_b2, att_b1, att_b2, M_, t0, t1);
    }

    int gblocks = (N_ + 7) / 8;
    gru_kernel<<<gblocks, 128>>>(node_feat, gru_w_ih, gru_w_hh, gru_b_ih, gru_b_hh, out, N_);
}

// round 12
// speedup vs baseline: 4.5816x; 4.5816x over previous
#include <cuda_runtime.h>
#include <cuda_fp16.h>
#include <cstdint>
#include <math.h>

#define DD 128
#define NPTHREADS 256
#define ETH 512
#define GTH 512

// Device scratch
__device__ float  g_agg[(size_t)50000 * 128];
__device__ float  g_P[(size_t)50000 * 256];
__device__ __half g_w1h[256 * 256];       // [n][k] n-major: W1 (state|eattr rows), msg|att
__device__ uint32_t g_gruh[768 * 64];     // [j][64 words] fp16 pairs, word-interleaved (w, w+4)

__device__ __forceinline__ float sigmoidf_fast(float x) {
    return 1.0f / (1.0f + __expf(-x));
}
__device__ __forceinline__ void mma_f16(float c[4], const unsigned a[4], const unsigned b[2]) {
    asm volatile(
        "mma.sync.aligned.m16n8k16.row.col.f32.f16.f16.f32 "
        "{%0,%1,%2,%3}, {%4,%5,%6,%7}, {%8,%9}, {%0,%1,%2,%3};"
        : "+f"(c[0]), "+f"(c[1]), "+f"(c[2]), "+f"(c[3])
        : "r"(a[0]), "r"(a[1]), "r"(a[2]), "r"(a[3]), "r"(b[0]), "r"(b[1]));
}
__device__ __forceinline__ uint32_t pack_h2(float lo, float hi) {
    __half2 h = __floats2half2_rn(lo, hi);
    return *(uint32_t*)&h;
}

__global__ void zero_agg_kernel() {
    size_t i = (size_t)blockIdx.x * blockDim.x + threadIdx.x;
    if (i < (size_t)50000 * 128) g_agg[i] = 0.0f;
}

// One-time weight staging.
__global__ void prep_kernel(const float* __restrict__ msg_w1,
                            const float* __restrict__ att_w1,
                            const float* __restrict__ gru_w_ih,   // [384][128]
                            const float* __restrict__ gru_w_hh)   // [384][128]
{
    int i = blockIdx.x * 256 + threadIdx.x;   // 0 .. 65535
    if (i < 65536) {            // g_w1h [256 n][256 k]
        int n = i >> 8, k = i & 255;
        int wrow = (k < 128) ? k : (k + 32);     // skip EF rows 128..159
        float v = (n < 128) ? msg_w1[wrow * 128 + n] : att_w1[wrow * 128 + (n - 128)];
        g_w1h[i] = __float2half_rn(v);
    }
    if (i < 49152) {            // g_gruh [768 j][64 words], interleaved (w, w+4) within 8-word groups
        int j = i >> 6, w = i & 63;
        int group = w >> 3, slot = w & 7;
        int owi = group * 8 + (slot >> 1) + (slot & 1) * 4;   // original word index
        int k = 2 * owi;
        const float* src = (j < 384) ? gru_w_ih + (size_t)j * 128
                                     : gru_w_hh + (size_t)(j - 384) * 128;
        g_gruh[(size_t)j * 64 + w] = pack_h2(src[k], src[k + 1]);
    }
}

// ===================== Node projection kernel (fp16 HMMA) =====================
#define NPXS 20
extern "C" __global__ void __launch_bounds__(NPTHREADS)
nodeproj_kernel(const float* __restrict__ node_feat,
                const float* __restrict__ node_attr,   // [2][N]
                const float* __restrict__ edge_attr,   // [N][128]
                const float* __restrict__ msg_w1,
                const float* __restrict__ att_w1,
                int N_)
{
    __shared__ uint32_t xs[64 * NPXS];
    __shared__ float wna[2][256];

    const int tid  = threadIdx.x;
    const int lane = tid & 31;
    const int wid  = tid >> 5;
    const int g    = lane >> 2;
    const int tg   = lane & 3;
    const int mg   = wid & 1;        // rows 32*mg
    const int ng   = wid >> 1;       // cols 64*ng
    const int n0   = blockIdx.x * 64;

    for (int c = tid; c < 256; c += NPTHREADS) {
        const float* w1 = (c < 128) ? msg_w1 : att_w1;
        int cc = c & 127;
        wna[0][c] = w1[288 * 128 + cc];
        wna[1][c] = w1[289 * 128 + cc];
    }

    float acc[2][8][4];
    #pragma unroll
    for (int mt = 0; mt < 2; ++mt)
        #pragma unroll
        for (int nt = 0; nt < 8; ++nt)
            #pragma unroll
            for (int c = 0; c < 4; ++c) acc[mt][nt][c] = 0.f;

    for (int s = 0; s < 8; ++s) {
        const int k0 = 32 * s;
        for (int idx = tid; idx < 64 * 16; idx += NPTHREADS) {
            int row = idx >> 4, w = idx & 15;
            int n = n0 + row;
            float v0 = 0.f, v1 = 0.f;
            if (n < N_) {
                int k = k0 + 2 * w;
                if (k < 128) {
                    v0 = node_feat[(size_t)n * 128 + k];
                    v1 = node_feat[(size_t)n * 128 + k + 1];
                } else {
                    v0 = edge_attr[(size_t)n * 128 + (k - 128)];
                    v1 = edge_attr[(size_t)n * 128 + (k - 128) + 1];
                }
            }
            xs[row * NPXS + w] = pack_h2(v0, v1);
        }
        __syncthreads();
        const int k0w = s * 16;
        #pragma unroll
        for (int ks = 0; ks < 2; ++ks) {
            const int klw = ks * 8;
            unsigned a[2][4];
            #pragma unroll
            for (int mt = 0; mt < 2; ++mt) {
                int row = 32 * mg + 16 * mt + g;
                a[mt][0] = xs[row * NPXS + klw + tg];
                a[mt][1] = xs[(row + 8) * NPXS + klw + tg];
                a[mt][2] = xs[row * NPXS + klw + tg + 4];
                a[mt][3] = xs[(row + 8) * NPXS + klw + tg + 4];
            }
            #pragma unroll
            for (int nt = 0; nt < 8; ++nt) {
                int n = 64 * ng + 8 * nt + g;
                const uint32_t* wrow = (const uint32_t*)(g_w1h + (size_t)n * 256);
                unsigned b[2];
                b[0] = __ldg(wrow + k0w + klw + tg);
                b[1] = __ldg(wrow + k0w + klw + tg + 4);
                mma_f16(acc[0][nt], a[0], b);
                mma_f16(acc[1][nt], a[1], b);
            }
        }
        __syncthreads();
    }

    #pragma unroll
    for (int mt = 0; mt < 2; ++mt)
        #pragma unroll
        for (int c = 0; c < 4; ++c) {
            int r = 32 * mg + 16 * mt + g + 8 * (c >> 1);
            int n = n0 + r;
            if (n >= N_) continue;
            float na0 = node_attr[n];
            float na1 = node_attr[N_ + n];
            #pragma unroll
            for (int nt = 0; nt < 8; ++nt) {
                int col = 64 * ng + 8 * nt + 2 * tg + (c & 1);
                g_P[(size_t)n * 256 + col] =
                    acc[mt][nt][c] + na0 * wna[0][col] + na1 * wna[1][col];
            }
        }
}

// ===================== Edge kernel (R10 form: persistent, fp16, 512 thr) =====================
#define W2_OFF   0
#define WEF_OFF  69632
#define XS_OFF   90112
#define H_OFF    95232
#define PRE_OFF  129024
#define SD_OFF   195584
#define B1_OFF   196096
#define B2_OFF   197120
#define EDGE_SMEM_BYTES 198144
#define LDW2W 68
#define LDWEFW 20
#define LDXSW 20
#define LDHW 132
#define LDP 260

extern "C" __global__ void __launch_bounds__(ETH, 1)
edge_kernel(const int*   __restrict__ edge,
            const float* __restrict__ edge_feat,
            const float* __restrict__ msg_w1, const float* __restrict__ msg_b1,
            const float* __restrict__ msg_w2, const float* __restrict__ msg_b2,
            const float* __restrict__ att_w1, const float* __restrict__ att_b1,
            const float* __restrict__ att_w2, const float* __restrict__ att_b2,
            int M_, int t0, int t1)
{
    extern __shared__ char smraw[];
    uint32_t* w232  = (uint32_t*)(smraw + W2_OFF);
    uint32_t* wef32 = (uint32_t*)(smraw + WEF_OFF);
    uint32_t* xs32  = (uint32_t*)(smraw + XS_OFF);
    uint32_t* h32   = (uint32_t*)(smraw + H_OFF);
    float*    pref  = (float*)(smraw + PRE_OFF);
    int*      sd    = (int*)(smraw + SD_OFF);
    float*    b1s   = (float*)(smraw + B1_OFF);
    float*    b2s   = (float*)(smraw + B2_OFF);
    __half*   w2h   = (__half*)(smraw + W2_OFF);
    __half*   wefh  = (__half*)(smraw + WEF_OFF);

    const int tid  = threadIdx.x;
    const int lane = tid & 31;
    const int wid  = tid >> 5;          // 0..15
    const int g    = lane >> 2;
    const int tg   = lane & 3;
    const int mg   = wid & 3;           // rows 16*mg
    const int ng   = wid >> 2;          // cols 64*ng
    const int br   = ng >> 1;           // 0=msg, 1=att
    const int koffw = br * 64;
    const int r0   = 16 * mg;
    const int c0   = 64 * ng;

    for (int idx = tid; idx < 256 * 128; idx += ETH) {
        int n = idx >> 7, k = idx & 127;
        float v = (n < 128) ? msg_w2[k * 128 + n] : att_w2[k * 128 + (n - 128)];
        w2h[n * 136 + k] = __float2half_rn(v);
    }
    for (int idx = tid; idx < 256 * 32; idx += ETH) {
        int n = idx >> 5, k = idx & 31;
        float v = (n < 128) ? msg_w1[(128 + k) * 128 + n] : att_w1[(128 + k) * 128 + (n - 128)];
        wefh[n * 40 + k] = __float2half_rn(v);
    }
    for (int c = tid; c < 256; c += ETH) {
        b1s[c] = (c < 128) ? msg_b1[c] : att_b1[c - 128];
        b2s[c] = (c < 128) ? msg_b2[c] : att_b2[c - 128];
    }
    __syncthreads();

    for (int t = t0 + blockIdx.x; t < t1; t += gridDim.x) {
        const int e0 = t << 6;

        if (tid < 64) {
            int ge = e0 + tid;
            int s = 0, d = 0;
            if (ge < M_) { s = edge[2 * ge]; d = edge[2 * ge + 1]; }
            sd[tid] = s;
            sd[64 + tid] = d;
        }
        for (int idx = tid; idx < 64 * 16; idx += ETH) {
            int row = idx >> 4, w = idx & 15;
            int ge = e0 + row;
            float v0 = 0.f, v1 = 0.f;
            if (ge < M_) {
                v0 = edge_feat[(size_t)ge * 32 + 2 * w];
                v1 = edge_feat[(size_t)ge * 32 + 2 * w + 1];
            }
            xs32[row * LDXSW + w] = pack_h2(v0, v1);
        }
        __syncthreads();

        for (int idx = tid; idx < 64 * 64; idx += ETH) {
            int row = idx >> 6, c4 = idx & 63;
            const float4* ps = (const float4*)(g_P + (size_t)sd[row] * 256) + c4;
            const float4* pd = (const float4*)(g_P + (size_t)sd[64 + row] * 256) + c4;
            float4 a = *ps, b = *pd;
            float4 r;
            r.x = a.x - b.x; r.y = a.y - b.y; r.z = a.z - b.z; r.w = a.w - b.w;
            *(float4*)(pref + row * LDP + c4 * 4) = r;
        }

        float acc[8][4];
        #pragma unroll
        for (int nt = 0; nt < 8; ++nt)
            #pragma unroll
            for (int c = 0; c < 4; ++c) acc[nt][c] = 0.f;

        #pragma unroll
        for (int ks = 0; ks < 2; ++ks) {
            const int k0w = ks * 8;
            unsigned a[4];
            a[0] = xs32[(r0 + g) * LDXSW + k0w + tg];
            a[1] = xs32[(r0 + g + 8) * LDXSW + k0w + tg];
            a[2] = xs32[(r0 + g) * LDXSW + k0w + tg + 4];
            a[3] = xs32[(r0 + g + 8) * LDXSW + k0w + tg + 4];
            #pragma unroll
            for (int nt = 0; nt < 8; ++nt) {
                int n = c0 + 8 * nt + g;
                unsigned b[2];
                b[0] = wef32[n * LDWEFW + k0w + tg];
                b[1] = wef32[n * LDWEFW + k0w + tg + 4];
                mma_f16(acc[nt], a, b);
            }
        }
        __syncthreads();

        #pragma unroll
        for (int c2 = 0; c2 < 2; ++c2) {
            int r = r0 + g + 8 * c2;
            #pragma unroll
            for (int nt = 0; nt < 8; ++nt) {
                int colb = c0 + 8 * nt + 2 * tg;
                float v0 = pref[r * LDP + colb]     + acc[nt][2 * c2]     + b1s[colb];
                float v1 = pref[r * LDP + colb + 1] + acc[nt][2 * c2 + 1] + b1s[colb + 1];
                h32[r * LDHW + (colb >> 1)] = pack_h2(fmaxf(v0, 0.f), fmaxf(v1, 0.f));
            }
        }
        __syncthreads();

        #pragma unroll
        for (int nt = 0; nt < 8; ++nt)
            #pragma unroll
            for (int c = 0; c < 4; ++c) acc[nt][c] = 0.f;

        #pragma unroll
        for (int ks = 0; ks < 8; ++ks) {
            const int k0w = ks * 8;
            unsigned a[4];
            a[0] = h32[(r0 + g) * LDHW + koffw + k0w + tg];
            a[1] = h32[(r0 + g + 8) * LDHW + koffw + k0w + tg];
            a[2] = h32[(r0 + g) * LDHW + koffw + k0w + tg + 4];
            a[3] = h32[(r0 + g + 8) * LDHW + koffw + k0w + tg + 4];
            #pragma unroll
            for (int nt = 0; nt < 8; ++nt) {
                int n = c0 + 8 * nt + g;
                unsigned b[2];
                b[0] = w232[n * LDW2W + k0w + tg];
                b[1] = w232[n * LDW2W + k0w + tg + 4];
                mma_f16(acc[nt], a, b);
            }
        }

        #pragma unroll
        for (int c = 0; c < 4; ++c) {
            int r = r0 + g + 8 * (c >> 1);
            #pragma unroll
            for (int nt = 0; nt < 8; ++nt) {
                int col = c0 + 8 * nt + 2 * tg + (c & 1);
                float v = acc[nt][c] + b2s[col];
                if (br) v = sigmoidf_fast(v);
                pref[r * LDP + col] = v;
            }
        }
        __syncthreads();

        for (int idx = tid; idx < 64 * 128; idx += ETH) {
            int row = idx >> 7, c = idx & 127;
            int ge = e0 + row;
            if (ge < M_) {
                float v = pref[row * LDP + c] * pref[row * LDP + 128 + c];
                atomicAdd(g_agg + (size_t)sd[64 + row] * 128 + c, v);
            }
        }
        __syncthreads();
    }
}

// ===================== GRU kernel (fp16 HMMA GEMM) =====================
// smem: as32 [64][68 w] fp16   17408 B
//       gi_s [64][388] f32     99328 B
//       gh_s [64][388] f32     99328 B
#define GAS_OFF 0
#define GI_OFF  17408
#define GH_OFF  116736
#define GRU_SMEM_BYTES 216064
#define GLDA 68
#define GLDS 388

extern "C" __global__ void __launch_bounds__(GTH, 1)
gru_kernel(const float* __restrict__ node_feat,
           const float* __restrict__ b_ih,
           const float* __restrict__ b_hh,
           float* __restrict__ out, int N_)
{
    extern __shared__ char smraw[];
    uint32_t* as32 = (uint32_t*)(smraw + GAS_OFF);
    float*    gi_s = (float*)(smraw + GI_OFF);
    float*    gh_s = (float*)(smraw + GH_OFF);

    const int tid  = threadIdx.x;
    const int lane = tid & 31;
    const int wid  = tid >> 5;       // 0..15
    const int g    = lane >> 2;
    const int tg   = lane & 3;
    const int mg   = wid & 3;        // rows 16*mg
    const int ng   = wid >> 2;       // cols 96*ng
    const int r0   = 16 * mg;
    const int c0   = 96 * ng;
    const int n0   = blockIdx.x * 64;

    float acc[12][4];

    #pragma unroll 1
    for (int phase = 0; phase < 2; ++phase) {
        const float* A = phase ? node_feat : g_agg;
        const int jbase = phase ? 384 : 0;
        const float* bias = phase ? b_hh : b_ih;
        float* dst = phase ? gh_s : gi_s;

        // load A [64][128] -> fp16 packed
        for (int idx = tid; idx < 64 * 64; idx += GTH) {
            int row = idx >> 6, w = idx & 63;
            int n = n0 + row;
            float v0 = 0.f, v1 = 0.f;
            if (n < N_) {
                const float2 p = *(const float2*)(A + (size_t)n * 128 + 2 * w);
                v0 = p.x; v1 = p.y;
            }
            as32[row * GLDA + w] = pack_h2(v0, v1);
        }
        __syncthreads();

        #pragma unroll
        for (int nt = 0; nt < 12; ++nt)
            #pragma unroll
            for (int c = 0; c < 4; ++c) acc[nt][c] = 0.f;

        #pragma unroll
        for (int ks = 0; ks < 8; ++ks) {
            const int k0w = ks * 8;
            unsigned a[4];
            a[0] = as32[(r0 + g) * GLDA + k0w + tg];
            a[1] = as32[(r0 + g + 8) * GLDA + k0w + tg];
            a[2] = as32[(r0 + g) * GLDA + k0w + tg + 4];
            a[3] = as32[(r0 + g + 8) * GLDA + k0w + tg + 4];
            #pragma unroll
            for (int nt = 0; nt < 12; ++nt) {
                int j = jbase + c0 + 8 * nt + g;
                uint2 bb = __ldg((const uint2*)(g_gruh + (size_t)j * 64 + k0w + 2 * tg));
                unsigned b[2] = { bb.x, bb.y };
                mma_f16(acc[nt], a, b);
            }
        }

        #pragma unroll
        for (int c = 0; c < 4; ++c) {
            int r = r0 + g + 8 * (c >> 1);
            #pragma unroll
            for (int nt = 0; nt < 12; ++nt) {
                int col = c0 + 8 * nt + 2 * tg + (c & 1);
                dst[r * GLDS + col] = acc[nt][c] + __ldg(bias + col);
            }
        }
        __syncthreads();
    }

    // gate + output
    for (int idx = tid; idx < 64 * 128; idx += GTH) {
        int n = idx >> 7, c = idx & 127;
        int gn = n0 + n;
        if (gn >= N_) continue;
        float ir = gi_s[n * GLDS + c];
        float iz = gi_s[n * GLDS + 128 + c];
        float in_ = gi_s[n * GLDS + 256 + c];
        float hr = gh_s[n * GLDS + c];
        float hz = gh_s[n * GLDS + 128 + c];
        float hn = gh_s[n * GLDS + 256 + c];
        float sv = node_feat[(size_t)gn * 128 + c];
        float r = sigmoidf_fast(ir + hr);
        float z = sigmoidf_fast(iz + hz);
        float nv = tanhf(in_ + r * hn);
        out[(size_t)gn * 128 + c] = (1.0f - z) * nv + z * sv;
    }
}

extern "C" void kernel_launch(void* const* d_in, const int* in_sizes, int n_in,
                              void* d_out, int out_size)
{
    const float* node_feat = (const float*)d_in[0];
    const int*   edge      = (const int*)  d_in[1];
    const float* edge_feat = (const float*)d_in[2];
    const float* node_attr = (const float*)d_in[3];
    const float* edge_attr = (const float*)d_in[4];
    const float* msg_w1    = (const float*)d_in[5];
    const float* msg_b1    = (const float*)d_in[6];
    const float* msg_w2    = (const float*)d_in[7];
    const float* msg_b2    = (const float*)d_in[8];
    const float* att_w1    = (const float*)d_in[9];
    const float* att_b1    = (const float*)d_in[10];
    const float* att_w2    = (const float*)d_in[11];
    const float* att_b2    = (const float*)d_in[12];
    const float* gru_w_ih  = (const float*)d_in[13];
    const float* gru_w_hh  = (const float*)d_in[14];
    const float* gru_b_ih  = (const float*)d_in[15];
    const float* gru_b_hh  = (const float*)d_in[16];
    float* out = (float*)d_out;

    int N_ = in_sizes[0] / DD;
    int M_ = in_sizes[1] / 2;

    cudaFuncSetAttribute(edge_kernel, cudaFuncAttributeMaxDynamicSharedMemorySize,
                         EDGE_SMEM_BYTES);
    cudaFuncSetAttribute(gru_kernel, cudaFuncAttributeMaxDynamicSharedMemorySize,
                         GRU_SMEM_BYTES);

    size_t tot = (size_t)N_ * DD;
    zero_agg_kernel<<<(int)((tot + 255) / 256), 256>>>();

    prep_kernel<<<256, 256>>>(msg_w1, att_w1, gru_w_ih, gru_w_hh);

    int nblocks = (N_ + 63) / 64;
    nodeproj_kernel<<<nblocks, NPTHREADS>>>(node_feat, node_attr, edge_attr,
                                            msg_w1, att_w1, N_);

    int ntiles = (M_ + 63) / 64;
    for (int q = 0; q < 4; ++q) {
        int t0 = (ntiles * q) / 4;
        int t1 = (ntiles * (q + 1)) / 4;
        int nt = t1 - t0;
        if (nt <= 0) continue;
        int egrid = nt < 148 ? nt : 148;
        edge_kernel<<<egrid, ETH, EDGE_SMEM_BYTES>>>(
            edge, edge_feat,
            msg_w1, msg_b1, msg_w2, msg_b2,
            att_w1, att_b1, att_w2, att_b2, M_, t0, t1);
    }

    int gblocks = (N_ + 63) / 64;
    gru_kernel<<<gblocks, GTH, GRU_SMEM_BYTES>>>(node_feat, gru_b_ih, gru_b_hh, out, N_);
}